// round 13
// baseline (speedup 1.0000x reference)
#include <cuda_runtime.h>
#include <cuda_fp16.h>
#include <cstdint>

// ---------------------------------------------------------------------------
// DARTSLayer as one fp16 tensor-core GEMM:
//   out[b,j] = sum_{p,i} W[p*64+i, j] * prim_p(x[b,i])
// R11 -> R12: fix staging coverage (256 threads stage all 128 rows), 8 warps
// x one 16-row m-tile each, STS.128 staging at the 4-wavefront minimum.
// Inner loop: LDS.128 B + ldmatrix.x4 A + 8 HMMA, primitives for p+1 staged
// concurrently (double-buffered SMEM tiles).
// ---------------------------------------------------------------------------

#define BATCH   65536
#define NIN     64
#define NOUT    64
#define NKK     28                  // K=448 / 16 per mma
#define WQUAD_N (NKK * 4 * 32)      // 3584 uint4 B-fragment quads
#define W_BYTES (WQUAD_N * 16)      // 57344
#define STAGE_B (128 * 128)         // 16384: 128 rows x 64 fp16 (128B rows)
#define SMEM_TOT (W_BYTES + 2 * STAGE_B)   // 90112

__device__ uint4 g_Wfrag[WQUAD_N];

// --------------------------- helpers ----------------------------------------

__device__ __forceinline__ uint32_t smem_u32(const void* p) {
    uint32_t a;
    asm("{ .reg .u64 t; cvta.to.shared.u64 t, %1; cvt.u32.u64 %0, t; }"
        : "=r"(a) : "l"(p));
    return a;
}

__device__ __forceinline__ uint32_t pack2(float lo, float hi) {
    uint32_t r;
    asm("cvt.rn.f16x2.f32 %0, %1, %2;" : "=r"(r) : "f"(hi), "f"(lo));
    return r;
}

__device__ __forceinline__ float frcp(float x) {
    float r;
    asm("rcp.approx.f32 %0, %1;" : "=f"(r) : "f"(x));
    return r;
}

__device__ __forceinline__ void mma16816(float* d, const uint32_t* a,
                                         uint32_t b0, uint32_t b1) {
    asm volatile(
        "mma.sync.aligned.m16n8k16.row.col.f32.f16.f16.f32 "
        "{%0,%1,%2,%3}, {%4,%5,%6,%7}, {%8,%9}, {%0,%1,%2,%3};"
        : "+f"(d[0]), "+f"(d[1]), "+f"(d[2]), "+f"(d[3])
        : "r"(a[0]), "r"(a[1]), "r"(a[2]), "r"(a[3]), "r"(b0), "r"(b1));
}

__device__ __forceinline__ float prim_eval(int p, float x) {
    switch (p) {
        case 0:  return x;            // linear
        case 1:  return x * x;        // power_two
        case 2:  return x * x * x;    // power_three
        case 3:  return __expf(x);    // exp
        case 4:  return __logf(x);    // ln
        case 5:  return frcp(x);      // reciprocal
        default: return __sinf(x);    // sin
    }
}

// --------------------------- W preparation -----------------------------------
// One thread per (i, j). Scatters softmax-gated weights as fp16 halves into
// the paired B-fragment layout:
//   uint4 element = (kk*4 + ntp)*32 + lane
//   word w = (nt&1)*2 + reg; reg0 holds k=2c,2c+1, reg1 k=2c+8,2c+9
//   n = (lane/4) + 8*nt, c = lane%4, nt = 2*ntp + (nt&1)

__global__ void darts_prep_kernel(const float* __restrict__ alphas,
                                  const float* __restrict__ coeffs) {
    int idx = blockIdx.x * blockDim.x + threadIdx.x;  // i*64 + j
    if (idx >= NIN * NOUT) return;
    int i = idx >> 6;
    int j = idx & 63;

    float a[8];
#pragma unroll
    for (int k = 0; k < 8; k++) a[k] = alphas[idx * 8 + k];
    float m = a[0];
#pragma unroll
    for (int k = 1; k < 8; k++) m = fmaxf(m, a[k]);
    float e[8], s = 0.0f;
#pragma unroll
    for (int k = 0; k < 8; k++) { e[k] = __expf(a[k] - m); s += e[k]; }
    float inv = 1.0f / s;

    __half* dst = (__half*)g_Wfrag;
#pragma unroll
    for (int p = 0; p < 7; p++) {
        float wv = e[p + 1] * inv * coeffs[idx * 8 + p + 1];
        int k    = p * 64 + i;
        int kk   = k >> 4;
        int kpos = k & 15;
        int nt   = j >> 3;
        int ntp  = nt >> 1;
        int lane = (j & 7) * 4 + ((kpos & 7) >> 1);
        int reg  = kpos >> 3;
        int half = kpos & 1;
        int word = (nt & 1) * 2 + reg;
        dst[((((kk * 4 + ntp) * 32 + lane) * 4) + word) * 2 + half] = __float2half_rn(wv);
    }
}

// --------------------------- main GEMM ---------------------------------------
// 256 threads (8 warps), 128-row CTA tile, grid 512, 2 CTAs/SM.
// Staging: thread (row = tid/2, half = tid&1) computes prim_p of its 32 x
// values and writes 4 x STS.128 (swizzled, ldmatrix-ready).
// GEMM: warp wid owns m-tile rows wid*16..+15, all 64 outputs.

__global__ void __launch_bounds__(256, 2)
darts_main_kernel(const float* __restrict__ x, float* __restrict__ out) {
    extern __shared__ char smem[];
    uint4* sW4 = (uint4*)smem;
    const uint32_t smem_base = smem_u32(smem);
    const uint32_t buf0 = smem_base + W_BYTES;
    const uint32_t buf1 = smem_base + W_BYTES + STAGE_B;

    int tid  = threadIdx.x;
    int wid  = tid >> 5;
    int lane = tid & 31;
    int r    = lane >> 2;   // 0..7
    int c    = lane & 3;    // 0..3

    // ---- x prefetch: thread holds half a row (32 f32) for all 7 p-phases
    int myrow = tid >> 1;          // 0..127
    int ihalf = tid & 1;
    float xv[32];
    {
        const float4* xp =
            (const float4*)(x + ((size_t)blockIdx.x * 128 + myrow) * NIN + ihalf * 32);
#pragma unroll
        for (int q = 0; q < 8; q++) {
            float4 t = xp[q];
            xv[q * 4 + 0] = t.x; xv[q * 4 + 1] = t.y;
            xv[q * 4 + 2] = t.z; xv[q * 4 + 3] = t.w;
        }
    }

    // ---- stage W fragments into SMEM (hides x LDG latency)
    {
        const uint4* src = (const uint4*)g_Wfrag;
        for (int u = tid; u < WQUAD_N; u += 256) sW4[u] = src[u];
    }

    // ---- staging STS.128 addresses (row-major 128B rows, chunk-XOR swizzle)
    const uint32_t srow_base = (uint32_t)myrow * 128;
    const uint32_t s_sw      = ((uint32_t)(myrow & 7)) << 4;

#define STAGE_P(P, BASE) do {                                                  \
        uint32_t _b = (BASE) + srow_base;                                      \
        _Pragma("unroll")                                                      \
        for (int v = 0; v < 4; v++) {                                          \
            uint32_t w0 = pack2(prim_eval((P), xv[v * 8 + 0]),                 \
                                prim_eval((P), xv[v * 8 + 1]));                \
            uint32_t w1 = pack2(prim_eval((P), xv[v * 8 + 2]),                 \
                                prim_eval((P), xv[v * 8 + 3]));                \
            uint32_t w2 = pack2(prim_eval((P), xv[v * 8 + 4]),                 \
                                prim_eval((P), xv[v * 8 + 5]));                \
            uint32_t w3 = pack2(prim_eval((P), xv[v * 8 + 6]),                 \
                                prim_eval((P), xv[v * 8 + 7]));                \
            uint32_t addr = _b + ((((uint32_t)ihalf * 64 + v * 16)) ^ s_sw);   \
            asm volatile("st.shared.v4.b32 [%0], {%1,%2,%3,%4};"               \
                         :: "r"(addr), "r"(w0), "r"(w1), "r"(w2), "r"(w3));    \
        }                                                                      \
    } while (0)

    // ---- ldmatrix addressing: lane -> (row, 16B khalf) of this warp's m-tile
    uint32_t llin, lsw;
    {
        uint32_t row = (uint32_t)(wid * 16 + (lane & 7) + ((lane >> 3) & 1) * 8);
        llin = row * 128 + ((lane >> 4) & 1) * 16;
        lsw  = (row & 7) << 4;
    }

    float acc[8][4];
#pragma unroll
    for (int nt = 0; nt < 8; nt++)
#pragma unroll
        for (int v = 0; v < 4; v++) acc[nt][v] = 0.0f;

    STAGE_P(0, buf0);
    __syncthreads();

#pragma unroll
    for (int p = 0; p < 7; p++) {
        // stage next p's primitives into the other buffer (overlaps with GEMM)
        if (p < 6) {
            if ((p + 1) & 1) STAGE_P(p + 1, buf1);
            else             STAGE_P(p + 1, buf0);
        }

        uint32_t abase = (p & 1) ? buf1 : buf0;
#pragma unroll
        for (int kk = 0; kk < 4; kk++) {
            const uint4* bp = sW4 + (size_t)((p * 4 + kk) * 4) * 32 + lane;
            uint4 b[4];
#pragma unroll
            for (int ntp = 0; ntp < 4; ntp++) b[ntp] = bp[ntp * 32];

            uint32_t A[4];
            {
                uint32_t addr = abase + ((llin + kk * 32) ^ lsw);
                asm volatile(
                    "ldmatrix.sync.aligned.m8n8.x4.shared.b16 {%0,%1,%2,%3}, [%4];"
                    : "=r"(A[0]), "=r"(A[1]), "=r"(A[2]), "=r"(A[3])
                    : "r"(addr));
            }

#pragma unroll
            for (int ntp = 0; ntp < 4; ntp++) {
                mma16816(acc[2 * ntp + 0], A, b[ntp].x, b[ntp].y);
                mma16816(acc[2 * ntp + 1], A, b[ntp].z, b[ntp].w);
            }
        }
        __syncthreads();
    }
#undef STAGE_P

    // ---- epilogue: c0/c1 -> row r, c2/c3 -> row 8 + r, cols nt*8 + 2c
    int warp_row0 = blockIdx.x * 128 + wid * 16;
#pragma unroll
    for (int hr = 0; hr < 2; hr++) {
        float* orow = out + (size_t)(warp_row0 + hr * 8 + r) * NOUT;
#pragma unroll
        for (int nt = 0; nt < 8; nt++) {
            float2 v;
            v.x = acc[nt][hr * 2 + 0];
            v.y = acc[nt][hr * 2 + 1];
            *(float2*)(orow + nt * 8 + 2 * c) = v;
        }
    }
}

// --------------------------- launch ------------------------------------------

extern "C" void kernel_launch(void* const* d_in, const int* in_sizes, int n_in,
                              void* d_out, int out_size) {
    (void)in_sizes; (void)n_in; (void)out_size;
    const float* x      = (const float*)d_in[0];
    const float* alphas = (const float*)d_in[1];
    const float* coeffs = (const float*)d_in[2];

    darts_prep_kernel<<<32, 128>>>(alphas, coeffs);

    cudaFuncSetAttribute(darts_main_kernel,
                         cudaFuncAttributeMaxDynamicSharedMemorySize, SMEM_TOT);
    darts_main_kernel<<<BATCH / 128, 256, SMEM_TOT>>>(x, (float*)d_out);
}